// round 4
// baseline (speedup 1.0000x reference)
#include <cuda_runtime.h>
#include <cstdint>

// Bilinear attention B=8, S=2048, H=1024 fp32, warp-level tf32 HMMA.
// All GEMM operands pre-split into interleaved float2{hi, lo} (3xTF32 trick):
//   hi = fp32 masked to tf32, lo = cvt.rna.tf32(x - hi)
// GEMM1 (xw = x@W)    : 3 terms, A,B pre-split, epilogue writes split xw.
// GEMM2 (scores)      : 3 terms, A,B pre-split.
// GEMM3 (ctx = attn@x): 2 terms (A = attn rounded to tf32 on the fly, B split)
//                       -- softmax output tolerates tf32 rounding (~1e-4).

// ---------------- scratch (device globals; no allocation) ----------------
__device__ float2 g_x2 [8ull * 2048ull * 1024ull];  // split x   [B,S,H]  128 MiB
__device__ float2 g_xt2[8ull * 1024ull * 2048ull];  // split x^T [B,H,S]  128 MiB
__device__ float2 g_wt2[1024ull * 1024ull];         // split W^T [H,H]      8 MiB
__device__ float2 g_xw2[8ull * 2048ull * 1024ull];  // split xw  [B,S,H]  128 MiB

// ---------------- helpers ----------------
__device__ __forceinline__ uint32_t smem_u32(const void* p) {
    uint32_t a;
    asm("{ .reg .u64 t; cvta.to.shared.u64 t, %1; cvt.u32.u64 %0, t; }" : "=r"(a) : "l"(p));
    return a;
}

#define CP_ASYNC16(dst, src) \
    asm volatile("cp.async.cg.shared.global [%0], [%1], 16;" :: "r"(dst), "l"(src) : "memory")
#define CP_COMMIT() asm volatile("cp.async.commit_group;" ::: "memory")
#define CP_WAIT(n)  asm volatile("cp.async.wait_group %0;" :: "n"(n) : "memory")

__device__ __forceinline__ float2 splitf(float v) {
    float h = __uint_as_float(__float_as_uint(v) & 0xFFFFE000u);
    uint32_t lo;
    asm("cvt.rna.tf32.f32 %0, %1;" : "=r"(lo) : "f"(v - h));
    return make_float2(h, __uint_as_float(lo));
}

__device__ __forceinline__ void mma8(float* c, const uint32_t* a, const uint32_t* b) {
    asm volatile(
        "mma.sync.aligned.m16n8k8.row.col.f32.tf32.tf32.f32 "
        "{%0,%1,%2,%3}, {%4,%5,%6,%7}, {%8,%9}, {%0,%1,%2,%3};"
        : "+f"(c[0]), "+f"(c[1]), "+f"(c[2]), "+f"(c[3])
        : "r"(a[0]), "r"(a[1]), "r"(a[2]), "r"(a[3]), "r"(b[0]), "r"(b[1]));
}

// ---------------- GEMM: C[m,n] = sum_k A[m,k] * B[n,k] ----------------
// CTA 128x128, K-chunk 32, 3-stage cp.async. 8 warps (2M x 4N), warp 64x32.
// Pre-split tiles: 128 rows x 32 float2, XOR-swizzled (c ^= (row&7)<<2):
// conflict-free for both 16B cp.async stores and LDS.64 fragment loads.
// Raw A tile (GEMM3): 128 rows x 32 floats padded to 36.

template <int TERMS, bool ASPLIT, bool CSPLIT>
__global__ __launch_bounds__(256, 1)
void gemm_tc(const void* __restrict__ Ag_, const void* __restrict__ Bg_,
             void* __restrict__ Cg_, int K, int N,
             long long sA, long long sB, long long sC)
{
    constexpr int ATB = ASPLIT ? 128 * 32 * 8 : 128 * 36 * 4;  // A tile bytes
    constexpr int STG = ATB + 128 * 32 * 8;                    // stage bytes

    extern __shared__ char smc[];
    const uint32_t sb = smem_u32(smc);

    const int tid  = threadIdx.x;
    const int wid  = tid >> 5;
    const int lane = tid & 31;
    const int g    = lane >> 2;
    const int tg   = lane & 3;
    const int wm   = (wid >> 2) * 64;
    const int wn   = (wid & 3) * 32;
    const int swz  = g << 2;          // fragment-row swizzle (row&7 == g)

    const float2* Bv = (const float2*)Bg_ + blockIdx.z * sB
                     + (long long)(blockIdx.x * 128) * K;

    float acc[4][4][4];
#pragma unroll
    for (int mt = 0; mt < 4; ++mt)
#pragma unroll
        for (int nt = 0; nt < 4; ++nt)
#pragma unroll
            for (int q = 0; q < 4; ++q) acc[mt][nt][q] = 0.f;

    const int nc = K >> 5;

    // ---- staging ----
    auto stage_load = [&](int i, int s) {
        const int kt = i << 5;
        const uint32_t st = sb + (uint32_t)(s * STG);
        if (ASPLIT) {
            const float2* A = (const float2*)Ag_ + blockIdx.z * sA
                            + (long long)(blockIdx.y * 128) * K;
            const int row = tid >> 4;
            const int c   = (tid & 15) * 2;
#pragma unroll
            for (int p = 0; p < 8; ++p) {
                const int r = row + p * 16;
                const uint32_t d = st + (uint32_t)((r * 32 + (c ^ ((r & 7) << 2))) * 8);
                CP_ASYNC16(d, A + (long long)r * K + kt + c);
            }
        } else {
            const float* A = (const float*)Ag_ + blockIdx.z * sA
                           + (long long)(blockIdx.y * 128) * K;
            const int row = tid >> 3;
            const int c4  = (tid & 7) * 4;
#pragma unroll
            for (int p = 0; p < 4; ++p) {
                const int r = row + p * 32;
                const uint32_t d = st + (uint32_t)((r * 36 + c4) * 4);
                CP_ASYNC16(d, A + (long long)r * K + kt + c4);
            }
        }
        {
            const int row = tid >> 4;
            const int c   = (tid & 15) * 2;
#pragma unroll
            for (int p = 0; p < 8; ++p) {
                const int r = row + p * 16;
                const uint32_t d = st + (uint32_t)(ATB + (r * 32 + (c ^ ((r & 7) << 2))) * 8);
                CP_ASYNC16(d, Bv + (long long)r * K + kt + c);
            }
        }
    };

    stage_load(0, 0); CP_COMMIT();
    if (nc > 1) stage_load(1, 1);
    CP_COMMIT();

    for (int i = 0; i < nc; ++i) {
        if (i + 2 < nc) { stage_load(i + 2, (i + 2) % 3); CP_COMMIT(); CP_WAIT(2); }
        else if (i + 1 < nc) { CP_WAIT(1); }
        else { CP_WAIT(0); }
        __syncthreads();

        const char* stg = smc + (i % 3) * STG;
        const float2* Bs2 = (const float2*)(stg + ATB);

#pragma unroll
        for (int ks = 0; ks < 4; ++ks) {
            const int k0 = ks * 8;
            const int ca = (k0 + tg) ^ swz;
            const int cb = (k0 + tg + 4) ^ swz;

            uint32_t ahi[4][4], alo[4][4];
            if (ASPLIT) {
                const float2* As2 = (const float2*)stg;
#pragma unroll
                for (int mt = 0; mt < 4; ++mt) {
                    const int r0 = wm + mt * 16 + g;
                    float2 v0 = As2[r0 * 32 + ca];
                    float2 v1 = As2[(r0 + 8) * 32 + ca];
                    float2 v2 = As2[r0 * 32 + cb];
                    float2 v3 = As2[(r0 + 8) * 32 + cb];
                    ahi[mt][0] = __float_as_uint(v0.x); alo[mt][0] = __float_as_uint(v0.y);
                    ahi[mt][1] = __float_as_uint(v1.x); alo[mt][1] = __float_as_uint(v1.y);
                    ahi[mt][2] = __float_as_uint(v2.x); alo[mt][2] = __float_as_uint(v2.y);
                    ahi[mt][3] = __float_as_uint(v3.x); alo[mt][3] = __float_as_uint(v3.y);
                }
            } else {
                const float* Asr = (const float*)stg;
#pragma unroll
                for (int mt = 0; mt < 4; ++mt) {
                    const int r0 = wm + mt * 16 + g;
                    float a0 = Asr[r0 * 36 + k0 + tg];
                    float a1 = Asr[(r0 + 8) * 36 + k0 + tg];
                    float a2 = Asr[r0 * 36 + k0 + tg + 4];
                    float a3 = Asr[(r0 + 8) * 36 + k0 + tg + 4];
                    asm("cvt.rna.tf32.f32 %0, %1;" : "=r"(ahi[mt][0]) : "f"(a0));
                    asm("cvt.rna.tf32.f32 %0, %1;" : "=r"(ahi[mt][1]) : "f"(a1));
                    asm("cvt.rna.tf32.f32 %0, %1;" : "=r"(ahi[mt][2]) : "f"(a2));
                    asm("cvt.rna.tf32.f32 %0, %1;" : "=r"(ahi[mt][3]) : "f"(a3));
                }
            }

            uint32_t bhi[4][2], blo[4][2];
#pragma unroll
            for (int nt = 0; nt < 4; ++nt) {
                const int n0 = wn + nt * 8 + g;
                float2 v0 = Bs2[n0 * 32 + ca];
                float2 v1 = Bs2[n0 * 32 + cb];
                bhi[nt][0] = __float_as_uint(v0.x); blo[nt][0] = __float_as_uint(v0.y);
                bhi[nt][1] = __float_as_uint(v1.x); blo[nt][1] = __float_as_uint(v1.y);
            }

#pragma unroll
            for (int mt = 0; mt < 4; ++mt)
#pragma unroll
                for (int nt = 0; nt < 4; ++nt) {
                    mma8(acc[mt][nt], ahi[mt], bhi[nt]);
                    if (TERMS >= 2) mma8(acc[mt][nt], ahi[mt], blo[nt]);
                    if (TERMS >= 3) mma8(acc[mt][nt], alo[mt], bhi[nt]);
                }
        }
        __syncthreads();
    }

    // ---- epilogue ----
    if (CSPLIT) {
        float2* C = (float2*)Cg_ + blockIdx.z * sC
                  + (long long)(blockIdx.y * 128 + wm) * N + blockIdx.x * 128 + wn;
#pragma unroll
        for (int mt = 0; mt < 4; ++mt)
#pragma unroll
            for (int nt = 0; nt < 4; ++nt) {
                const int r0 = mt * 16 + g;
                const int c0 = nt * 8 + 2 * tg;
                float2 p0 = splitf(acc[mt][nt][0]), p1 = splitf(acc[mt][nt][1]);
                float2 p2 = splitf(acc[mt][nt][2]), p3 = splitf(acc[mt][nt][3]);
                *(float4*)&C[(long long)r0 * N + c0]       = make_float4(p0.x, p0.y, p1.x, p1.y);
                *(float4*)&C[(long long)(r0 + 8) * N + c0] = make_float4(p2.x, p2.y, p3.x, p3.y);
            }
    } else {
        float* C = (float*)Cg_ + blockIdx.z * sC
                 + (long long)(blockIdx.y * 128 + wm) * N + blockIdx.x * 128 + wn;
#pragma unroll
        for (int mt = 0; mt < 4; ++mt)
#pragma unroll
            for (int nt = 0; nt < 4; ++nt) {
                const int r0 = mt * 16 + g;
                const int c0 = nt * 8 + 2 * tg;
                *(float2*)&C[(long long)r0 * N + c0] =
                    make_float2(acc[mt][nt][0], acc[mt][nt][1]);
                *(float2*)&C[(long long)(r0 + 8) * N + c0] =
                    make_float2(acc[mt][nt][2], acc[mt][nt][3]);
            }
    }
}

// ---------------- pre-split (elementwise), 4 elems/thread ----------------
__global__ __launch_bounds__(256)
void split_pairs(const float4* __restrict__ in, float4* __restrict__ out, long long n4)
{
    const long long i = (long long)blockIdx.x * blockDim.x + threadIdx.x;
    if (i >= n4) return;
    float4 v = in[i];
    float2 a = splitf(v.x), b = splitf(v.y), c = splitf(v.z), d = splitf(v.w);
    out[2 * i]     = make_float4(a.x, a.y, b.x, b.y);
    out[2 * i + 1] = make_float4(c.x, c.y, d.x, d.y);
}

// ------------- transpose + split: out2[c][r] = split(in[r][c]) -------------
__global__ __launch_bounds__(256)
void transpose_split(const float* __restrict__ in, float2* __restrict__ out, int R, int C)
{
    __shared__ float t[32][33];
    in  += (long long)blockIdx.z * R * C;
    out += (long long)blockIdx.z * R * C;
    const int c0 = blockIdx.x * 32, r0 = blockIdx.y * 32;
#pragma unroll
    for (int dy = 0; dy < 32; dy += 8)
        t[threadIdx.y + dy][threadIdx.x] =
            in[(long long)(r0 + threadIdx.y + dy) * C + c0 + threadIdx.x];
    __syncthreads();
#pragma unroll
    for (int dy = 0; dy < 32; dy += 8)
        out[(long long)(c0 + threadIdx.y + dy) * R + r0 + threadIdx.x] =
            splitf(t[threadIdx.x][threadIdx.y + dy]);
}

// ---------------- softmax over rows of length 2048, in place ----------------
__global__ __launch_bounds__(256)
void softmax_rows(float* __restrict__ data)
{
    const int S = 2048;
    float* p = data + (long long)blockIdx.x * S;
    const int tid = threadIdx.x;

    float4 v0 = ((const float4*)p)[tid];
    float4 v1 = ((const float4*)p)[tid + 256];

    float m = fmaxf(fmaxf(fmaxf(v0.x, v0.y), fmaxf(v0.z, v0.w)),
                    fmaxf(fmaxf(v1.x, v1.y), fmaxf(v1.z, v1.w)));

    __shared__ float red[8];
#pragma unroll
    for (int o = 16; o > 0; o >>= 1) m = fmaxf(m, __shfl_xor_sync(~0u, m, o));
    if ((tid & 31) == 0) red[tid >> 5] = m;
    __syncthreads();
    {
        float t = (tid < 8) ? red[tid & 7] : -1e30f;
#pragma unroll
        for (int o = 4; o > 0; o >>= 1) t = fmaxf(t, __shfl_xor_sync(~0u, t, o));
        __syncthreads();
        if (tid == 0) red[0] = t;
        __syncthreads();
        m = red[0];
    }

    v0.x = __expf(v0.x - m); v0.y = __expf(v0.y - m);
    v0.z = __expf(v0.z - m); v0.w = __expf(v0.w - m);
    v1.x = __expf(v1.x - m); v1.y = __expf(v1.y - m);
    v1.w = __expf(v1.w - m); v1.z = __expf(v1.z - m);

    float s = v0.x + v0.y + v0.z + v0.w + v1.x + v1.y + v1.z + v1.w;
#pragma unroll
    for (int o = 16; o > 0; o >>= 1) s += __shfl_xor_sync(~0u, s, o);
    __syncthreads();
    if ((tid & 31) == 0) red[tid >> 5] = s;
    __syncthreads();
    {
        float t = (tid < 8) ? red[tid & 7] : 0.f;
#pragma unroll
        for (int o = 4; o > 0; o >>= 1) t += __shfl_xor_sync(~0u, t, o);
        __syncthreads();
        if (tid == 0) red[0] = t;
        __syncthreads();
        s = red[0];
    }

    const float inv = 1.0f / s;
    v0.x *= inv; v0.y *= inv; v0.z *= inv; v0.w *= inv;
    v1.x *= inv; v1.y *= inv; v1.z *= inv; v1.w *= inv;

    ((float4*)p)[tid]       = v0;
    ((float4*)p)[tid + 256] = v1;
}

// ---------------- launch ----------------
extern "C" void kernel_launch(void* const* d_in, const int* in_sizes, int n_in,
                              void* d_out, int out_size)
{
    const float* x = (const float*)d_in[0];   // [8,2048,1024]
    const float* w = (const float*)d_in[1];   // [1024,1024]
    float* ctx  = (float*)d_out;              // [8,2048,1024]
    float* attn = (float*)d_out + 16777216LL; // [8,2048,2048]

    float2 *x2, *xt2, *wt2, *xw2;
    cudaGetSymbolAddress((void**)&x2,  g_x2);
    cudaGetSymbolAddress((void**)&xt2, g_xt2);
    cudaGetSymbolAddress((void**)&wt2, g_wt2);
    cudaGetSymbolAddress((void**)&xw2, g_xw2);

    const int B = 8, S = 2048, H = 1024;

    const int SM_SPLIT = 3 * (128 * 32 * 8 + 128 * 32 * 8);  // 196608
    const int SM_RAW   = 3 * (128 * 36 * 4 + 128 * 32 * 8);  // 153600
    cudaFuncSetAttribute(gemm_tc<3, true,  true >, cudaFuncAttributeMaxDynamicSharedMemorySize, SM_SPLIT);
    cudaFuncSetAttribute(gemm_tc<3, true,  false>, cudaFuncAttributeMaxDynamicSharedMemorySize, SM_SPLIT);
    cudaFuncSetAttribute(gemm_tc<2, false, false>, cudaFuncAttributeMaxDynamicSharedMemorySize, SM_RAW);

    // pre-splits
    {
        long long n4 = (long long)B * S * H / 4;
        split_pairs<<<(unsigned)((n4 + 255) / 256), 256>>>((const float4*)x, (float4*)x2, n4);
    }
    transpose_split<<<dim3(H / 32, S / 32, B), dim3(32, 8)>>>(x, xt2, S, H);
    transpose_split<<<dim3(H / 32, H / 32, 1), dim3(32, 8)>>>(w, wt2, H, H);

    // 1) xw = x @ W  -> split xw2.  A=x2 [B*S,H], B=wt2 [H,H]
    gemm_tc<3, true, true><<<dim3(H / 128, (B * S) / 128, 1), 256, SM_SPLIT>>>(
        x2, wt2, xw2, H, H, 0, 0, 0);

    // 2) scores = xw @ x^T -> attn buffer.  A=xw2, B=x2 per batch
    gemm_tc<3, true, false><<<dim3(S / 128, S / 128, B), 256, SM_SPLIT>>>(
        xw2, x2, attn, H, S,
        (long long)S * H, (long long)S * H, (long long)S * S);

    // 3) softmax in place
    softmax_rows<<<B * S, 256>>>(attn);

    // 4) ctx = attn @ x.  A=attn raw [S,S] (tf32 on the fly), B=xt2 [H,S]
    gemm_tc<2, false, false><<<dim3(H / 128, S / 128, B), 256, SM_RAW>>>(
        attn, xt2, ctx, S, H,
        (long long)S * S, (long long)S * H, (long long)S * H);
}

// round 5
// speedup vs baseline: 1.0727x; 1.0727x over previous
#include <cuda_runtime.h>
#include <cstdint>

// Bilinear attention B=8, S=2048, H=1024 fp32, warp-level tf32 HMMA, 3xTF32.
// hi/lo parts stored as SEPARATE float arrays (global) and SEPARATE PAD=36
// tiles (smem) -> mainloop is pure conflict-free LDS.32 + HMMA (no split ALU).
// GEMM1 (xw=x@W), GEMM2 (scores): 3 terms. GEMM3 (ctx=attn@x): 2 terms
// (attn rounded to tf32 on the fly; softmax output tolerates it, ~1e-4).

// ---------------- scratch (device globals; no allocation) ----------------
#define NBS (8ull * 2048ull * 1024ull)
__device__ float g_xh [NBS], g_xl [NBS];    // split x    [B,S,H]
__device__ float g_xth[NBS], g_xtl[NBS];    // split x^T  [B,H,S]
__device__ float g_wth[1024ull * 1024ull], g_wtl[1024ull * 1024ull];  // W^T
__device__ float g_xwh[NBS], g_xwl[NBS];    // split xw   [B,S,H]

// ---------------- helpers ----------------
__device__ __forceinline__ uint32_t smem_u32(const void* p) {
    uint32_t a;
    asm("{ .reg .u64 t; cvta.to.shared.u64 t, %1; cvt.u32.u64 %0, t; }" : "=r"(a) : "l"(p));
    return a;
}

#define CP_ASYNC16(dst, src) \
    asm volatile("cp.async.cg.shared.global [%0], [%1], 16;" :: "r"(dst), "l"(src) : "memory")
#define CP_COMMIT() asm volatile("cp.async.commit_group;" ::: "memory")
#define CP_WAIT(n)  asm volatile("cp.async.wait_group %0;" :: "n"(n) : "memory")

__device__ __forceinline__ float2 splitf(float v) {
    float h = __uint_as_float(__float_as_uint(v) & 0xFFFFE000u);
    uint32_t lo;
    asm("cvt.rna.tf32.f32 %0, %1;" : "=r"(lo) : "f"(v - h));
    return make_float2(h, __uint_as_float(lo));
}

__device__ __forceinline__ void mma8(float* c, const uint32_t* a, const uint32_t* b) {
    asm volatile(
        "mma.sync.aligned.m16n8k8.row.col.f32.tf32.tf32.f32 "
        "{%0,%1,%2,%3}, {%4,%5,%6,%7}, {%8,%9}, {%0,%1,%2,%3};"
        : "+f"(c[0]), "+f"(c[1]), "+f"(c[2]), "+f"(c[3])
        : "r"(a[0]), "r"(a[1]), "r"(a[2]), "r"(a[3]), "r"(b[0]), "r"(b[1]));
}

// ---------------- GEMM: C[m,n] = sum_k A[m,k] * B[n,k] ----------------
// CTA 128x128, K-chunk 32, 2-stage cp.async. 8 warps (2M x 4N), warp 64x32.
// All smem tiles: 128 rows x 32 floats, rows padded to 36 (conflict-free).
#define PAD  36
#define TILB (128 * PAD * 4)   // 18432 bytes per tile

template <int TERMS, bool ASPLIT, bool CSPLIT>
__global__ __launch_bounds__(256, 1)
void gemm_tc(const float* __restrict__ Ahg, const float* __restrict__ Alg,
             const float* __restrict__ Bhg, const float* __restrict__ Blg,
             float* __restrict__ Cg, float* __restrict__ C2g,
             int K, int N, long long sA, long long sB, long long sC)
{
    constexpr int T_AH = 0;
    constexpr int T_AL = TILB;                      // unused if !ASPLIT
    constexpr int T_BH = ASPLIT ? 2 * TILB : TILB;
    constexpr int T_BL = T_BH + TILB;
    constexpr int STG  = T_BL + TILB;               // stage bytes

    extern __shared__ char smc[];
    const uint32_t sb = smem_u32(smc);

    const int tid  = threadIdx.x;
    const int wid  = tid >> 5;
    const int lane = tid & 31;
    const int g    = lane >> 2;
    const int tg   = lane & 3;
    const int wm   = (wid >> 2) * 64;
    const int wn   = (wid & 3) * 32;

    const long long aoff = blockIdx.z * sA + (long long)(blockIdx.y * 128) * K;
    const long long boff = blockIdx.z * sB + (long long)(blockIdx.x * 128) * K;
    const float* Ah = Ahg + aoff;
    const float* Al = Alg + aoff;
    const float* Bh = Bhg + boff;
    const float* Bl = Blg + boff;

    float acc[4][4][4];
#pragma unroll
    for (int mt = 0; mt < 4; ++mt)
#pragma unroll
        for (int nt = 0; nt < 4; ++nt)
#pragma unroll
            for (int q = 0; q < 4; ++q) acc[mt][nt][q] = 0.f;

    const int nc = K >> 5;
    const int lr = tid >> 3;         // 0..31
    const int lc = (tid & 7) * 4;    // 0..28

    auto stage_load = [&](int i, int s) {
        const int kt = i << 5;
        const uint32_t st = sb + (uint32_t)(s * STG);
#pragma unroll
        for (int p = 0; p < 4; ++p) {
            const int r = lr + p * 32;
            const uint32_t off = (uint32_t)((r * PAD + lc) * 4);
            const long long gi = (long long)r * K + kt + lc;
            CP_ASYNC16(st + T_AH + off, Ah + gi);
            if (ASPLIT) CP_ASYNC16(st + T_AL + off, Al + gi);
            CP_ASYNC16(st + T_BH + off, Bh + gi);
            CP_ASYNC16(st + T_BL + off, Bl + gi);
        }
    };

    stage_load(0, 0); CP_COMMIT();
    if (nc > 1) { stage_load(1, 1); }
    CP_COMMIT();

    for (int i = 0; i < nc; ++i) {
        if (i + 2 < nc) { CP_WAIT(1); } else { CP_WAIT(0); }
        __syncthreads();

        const char* stg = smc + (i & 1) * STG;
        const float* AHs = (const float*)(stg + T_AH);
        const float* ALs = (const float*)(stg + T_AL);
        const float* BHs = (const float*)(stg + T_BH);
        const float* BLs = (const float*)(stg + T_BL);

#pragma unroll
        for (int ks = 0; ks < 4; ++ks) {
            const int k0 = ks * 8;

            uint32_t ahi[4][4], alo[4][4];
#pragma unroll
            for (int mt = 0; mt < 4; ++mt) {
                const int r0 = wm + mt * 16 + g;
                const int i00 = r0 * PAD + k0 + tg;
                const int i10 = (r0 + 8) * PAD + k0 + tg;
                if (ASPLIT) {
                    ahi[mt][0] = __float_as_uint(AHs[i00]);
                    ahi[mt][1] = __float_as_uint(AHs[i10]);
                    ahi[mt][2] = __float_as_uint(AHs[i00 + 4]);
                    ahi[mt][3] = __float_as_uint(AHs[i10 + 4]);
                    alo[mt][0] = __float_as_uint(ALs[i00]);
                    alo[mt][1] = __float_as_uint(ALs[i10]);
                    alo[mt][2] = __float_as_uint(ALs[i00 + 4]);
                    alo[mt][3] = __float_as_uint(ALs[i10 + 4]);
                } else {
                    asm("cvt.rna.tf32.f32 %0, %1;" : "=r"(ahi[mt][0]) : "f"(AHs[i00]));
                    asm("cvt.rna.tf32.f32 %0, %1;" : "=r"(ahi[mt][1]) : "f"(AHs[i10]));
                    asm("cvt.rna.tf32.f32 %0, %1;" : "=r"(ahi[mt][2]) : "f"(AHs[i00 + 4]));
                    asm("cvt.rna.tf32.f32 %0, %1;" : "=r"(ahi[mt][3]) : "f"(AHs[i10 + 4]));
                }
            }

            uint32_t bhi[4][2], blo[4][2];
#pragma unroll
            for (int nt = 0; nt < 4; ++nt) {
                const int n0 = (wn + nt * 8 + g) * PAD + k0 + tg;
                bhi[nt][0] = __float_as_uint(BHs[n0]);
                bhi[nt][1] = __float_as_uint(BHs[n0 + 4]);
                blo[nt][0] = __float_as_uint(BLs[n0]);
                blo[nt][1] = __float_as_uint(BLs[n0 + 4]);
            }

#pragma unroll
            for (int mt = 0; mt < 4; ++mt)
#pragma unroll
                for (int nt = 0; nt < 4; ++nt) {
                    mma8(acc[mt][nt], ahi[mt], bhi[nt]);
                    if (TERMS >= 2) mma8(acc[mt][nt], ahi[mt], blo[nt]);
                    if (TERMS >= 3) mma8(acc[mt][nt], alo[mt], bhi[nt]);
                }
        }
        __syncthreads();
        if (i + 2 < nc) { stage_load(i + 2, i & 1); CP_COMMIT(); }
    }

    // ---- epilogue ----
    const long long crow = blockIdx.z * sC
                         + (long long)(blockIdx.y * 128 + wm) * N + blockIdx.x * 128 + wn;
    if (CSPLIT) {
        float* C  = Cg  + crow;
        float* C2 = C2g + crow;
#pragma unroll
        for (int mt = 0; mt < 4; ++mt)
#pragma unroll
            for (int nt = 0; nt < 4; ++nt) {
                const long long r0 = (long long)(mt * 16 + g) * N + nt * 8 + 2 * tg;
                const long long r1 = r0 + 8LL * N;
                float2 p0 = splitf(acc[mt][nt][0]), p1 = splitf(acc[mt][nt][1]);
                float2 p2 = splitf(acc[mt][nt][2]), p3 = splitf(acc[mt][nt][3]);
                *(float2*)&C [r0] = make_float2(p0.x, p1.x);
                *(float2*)&C2[r0] = make_float2(p0.y, p1.y);
                *(float2*)&C [r1] = make_float2(p2.x, p3.x);
                *(float2*)&C2[r1] = make_float2(p2.y, p3.y);
            }
    } else {
        float* C = Cg + crow;
#pragma unroll
        for (int mt = 0; mt < 4; ++mt)
#pragma unroll
            for (int nt = 0; nt < 4; ++nt) {
                const long long r0 = (long long)(mt * 16 + g) * N + nt * 8 + 2 * tg;
                const long long r1 = r0 + 8LL * N;
                *(float2*)&C[r0] = make_float2(acc[mt][nt][0], acc[mt][nt][1]);
                *(float2*)&C[r1] = make_float2(acc[mt][nt][2], acc[mt][nt][3]);
            }
    }
}

// ---------------- pre-split into two arrays ----------------
__global__ __launch_bounds__(256)
void split_two(const float4* __restrict__ in, float4* __restrict__ oh,
               float4* __restrict__ ol, long long n4)
{
    const long long i = (long long)blockIdx.x * blockDim.x + threadIdx.x;
    if (i >= n4) return;
    float4 v = in[i];
    float2 a = splitf(v.x), b = splitf(v.y), c = splitf(v.z), d = splitf(v.w);
    oh[i] = make_float4(a.x, b.x, c.x, d.x);
    ol[i] = make_float4(a.y, b.y, c.y, d.y);
}

// ------- transpose + split: outh/outl[c][r] = split(in[r][c]) -------
__global__ __launch_bounds__(256)
void transpose_split2(const float* __restrict__ in, float* __restrict__ outh,
                      float* __restrict__ outl, int R, int C)
{
    __shared__ float t[32][33];
    const long long zo = (long long)blockIdx.z * R * C;
    in += zo; outh += zo; outl += zo;
    const int c0 = blockIdx.x * 32, r0 = blockIdx.y * 32;
#pragma unroll
    for (int dy = 0; dy < 32; dy += 8)
        t[threadIdx.y + dy][threadIdx.x] =
            in[(long long)(r0 + threadIdx.y + dy) * C + c0 + threadIdx.x];
    __syncthreads();
#pragma unroll
    for (int dy = 0; dy < 32; dy += 8) {
        float2 s = splitf(t[threadIdx.x][threadIdx.y + dy]);
        const long long o = (long long)(c0 + threadIdx.y + dy) * R + r0 + threadIdx.x;
        outh[o] = s.x;
        outl[o] = s.y;
    }
}

// ---------------- softmax over rows of length 2048, in place ----------------
__global__ __launch_bounds__(256)
void softmax_rows(float* __restrict__ data)
{
    const int S = 2048;
    float* p = data + (long long)blockIdx.x * S;
    const int tid = threadIdx.x;

    float4 v0 = ((const float4*)p)[tid];
    float4 v1 = ((const float4*)p)[tid + 256];

    float m = fmaxf(fmaxf(fmaxf(v0.x, v0.y), fmaxf(v0.z, v0.w)),
                    fmaxf(fmaxf(v1.x, v1.y), fmaxf(v1.z, v1.w)));

    __shared__ float red[8];
#pragma unroll
    for (int o = 16; o > 0; o >>= 1) m = fmaxf(m, __shfl_xor_sync(~0u, m, o));
    if ((tid & 31) == 0) red[tid >> 5] = m;
    __syncthreads();
    {
        float t = (tid < 8) ? red[tid & 7] : -1e30f;
#pragma unroll
        for (int o = 4; o > 0; o >>= 1) t = fmaxf(t, __shfl_xor_sync(~0u, t, o));
        __syncthreads();
        if (tid == 0) red[0] = t;
        __syncthreads();
        m = red[0];
    }

    v0.x = __expf(v0.x - m); v0.y = __expf(v0.y - m);
    v0.z = __expf(v0.z - m); v0.w = __expf(v0.w - m);
    v1.x = __expf(v1.x - m); v1.y = __expf(v1.y - m);
    v1.z = __expf(v1.z - m); v1.w = __expf(v1.w - m);

    float s = v0.x + v0.y + v0.z + v0.w + v1.x + v1.y + v1.z + v1.w;
#pragma unroll
    for (int o = 16; o > 0; o >>= 1) s += __shfl_xor_sync(~0u, s, o);
    __syncthreads();
    if ((tid & 31) == 0) red[tid >> 5] = s;
    __syncthreads();
    {
        float t = (tid < 8) ? red[tid & 7] : 0.f;
#pragma unroll
        for (int o = 4; o > 0; o >>= 1) t += __shfl_xor_sync(~0u, t, o);
        __syncthreads();
        if (tid == 0) red[0] = t;
        __syncthreads();
        s = red[0];
    }

    const float inv = 1.0f / s;
    v0.x *= inv; v0.y *= inv; v0.z *= inv; v0.w *= inv;
    v1.x *= inv; v1.y *= inv; v1.z *= inv; v1.w *= inv;

    ((float4*)p)[tid]       = v0;
    ((float4*)p)[tid + 256] = v1;
}

// ---------------- launch ----------------
extern "C" void kernel_launch(void* const* d_in, const int* in_sizes, int n_in,
                              void* d_out, int out_size)
{
    const float* x = (const float*)d_in[0];   // [8,2048,1024]
    const float* w = (const float*)d_in[1];   // [1024,1024]
    float* ctx  = (float*)d_out;              // [8,2048,1024]
    float* attn = (float*)d_out + 16777216LL; // [8,2048,2048]

    float *xh, *xl, *xth, *xtl, *wth, *wtl, *xwh, *xwl;
    cudaGetSymbolAddress((void**)&xh,  g_xh);
    cudaGetSymbolAddress((void**)&xl,  g_xl);
    cudaGetSymbolAddress((void**)&xth, g_xth);
    cudaGetSymbolAddress((void**)&xtl, g_xtl);
    cudaGetSymbolAddress((void**)&wth, g_wth);
    cudaGetSymbolAddress((void**)&wtl, g_wtl);
    cudaGetSymbolAddress((void**)&xwh, g_xwh);
    cudaGetSymbolAddress((void**)&xwl, g_xwl);

    const int B = 8, S = 2048, H = 1024;

    const int SM_SPLIT = 2 * 4 * TILB;   // 147456
    const int SM_RAW   = 2 * 3 * TILB;   // 110592
    cudaFuncSetAttribute(gemm_tc<3, true,  true >, cudaFuncAttributeMaxDynamicSharedMemorySize, SM_SPLIT);
    cudaFuncSetAttribute(gemm_tc<3, true,  false>, cudaFuncAttributeMaxDynamicSharedMemorySize, SM_SPLIT);
    cudaFuncSetAttribute(gemm_tc<2, false, false>, cudaFuncAttributeMaxDynamicSharedMemorySize, SM_RAW);

    // pre-splits
    {
        long long n4 = (long long)B * S * H / 4;
        split_two<<<(unsigned)((n4 + 255) / 256), 256>>>(
            (const float4*)x, (float4*)xh, (float4*)xl, n4);
    }
    transpose_split2<<<dim3(H / 32, S / 32, B), dim3(32, 8)>>>(x, xth, xtl, S, H);
    transpose_split2<<<dim3(H / 32, H / 32, 1), dim3(32, 8)>>>(w, wth, wtl, H, H);

    // 1) xw = x @ W -> split xwh/xwl.
    gemm_tc<3, true, true><<<dim3(H / 128, (B * S) / 128, 1), 256, SM_SPLIT>>>(
        xh, xl, wth, wtl, xwh, xwl, H, H, 0, 0, 0);

    // 2) scores = xw @ x^T -> attn buffer (per batch).
    gemm_tc<3, true, false><<<dim3(S / 128, S / 128, B), 256, SM_SPLIT>>>(
        xwh, xwl, xh, xl, attn, nullptr, H, S,
        (long long)S * H, (long long)S * H, (long long)S * S);

    // 3) softmax in place
    softmax_rows<<<B * S, 256>>>(attn);

    // 4) ctx = attn @ x. A raw (tf32 on the fly), 2 terms.
    gemm_tc<2, false, false><<<dim3(H / 128, S / 128, B), 256, SM_RAW>>>(
        attn, nullptr, xth, xtl, ctx, nullptr, S, H,
        (long long)S * S, (long long)S * H, (long long)S * H);
}

// round 6
// speedup vs baseline: 1.0961x; 1.0218x over previous
#include <cuda_runtime.h>
#include <cstdint>

// Bilinear attention B=8, S=2048, H=1024 fp32, warp-level tf32 HMMA, 3xTF32.
// hi/lo stored as separate float arrays; smem tiles PAD=36 (conflict-free).
// R6: CTA tile 128x256, warp tile 64x64 -> 85 B smem per HMMA (was 128).
// GEMM1 (xw=x@W), GEMM2 (scores): 3 terms. GEMM3 (ctx=attn@x): 2 terms.

// ---------------- scratch (device globals; no allocation) ----------------
#define NBS (8ull * 2048ull * 1024ull)
__device__ float g_xh [NBS], g_xl [NBS];    // split x    [B,S,H]
__device__ float g_xth[NBS], g_xtl[NBS];    // split x^T  [B,H,S]
__device__ float g_wth[1024ull * 1024ull], g_wtl[1024ull * 1024ull];  // W^T
__device__ float g_xwh[NBS], g_xwl[NBS];    // split xw   [B,S,H]

// ---------------- helpers ----------------
__device__ __forceinline__ uint32_t smem_u32(const void* p) {
    uint32_t a;
    asm("{ .reg .u64 t; cvta.to.shared.u64 t, %1; cvt.u32.u64 %0, t; }" : "=r"(a) : "l"(p));
    return a;
}

#define CP_ASYNC16(dst, src) \
    asm volatile("cp.async.cg.shared.global [%0], [%1], 16;" :: "r"(dst), "l"(src) : "memory")
#define CP_COMMIT() asm volatile("cp.async.commit_group;" ::: "memory")
#define CP_WAIT(n)  asm volatile("cp.async.wait_group %0;" :: "n"(n) : "memory")

__device__ __forceinline__ float2 splitf(float v) {
    float h = __uint_as_float(__float_as_uint(v) & 0xFFFFE000u);
    uint32_t lo;
    asm("cvt.rna.tf32.f32 %0, %1;" : "=r"(lo) : "f"(v - h));
    return make_float2(h, __uint_as_float(lo));
}

__device__ __forceinline__ void mma8(float* c, const uint32_t* a, const uint32_t* b) {
    asm volatile(
        "mma.sync.aligned.m16n8k8.row.col.f32.tf32.tf32.f32 "
        "{%0,%1,%2,%3}, {%4,%5,%6,%7}, {%8,%9}, {%0,%1,%2,%3};"
        : "+f"(c[0]), "+f"(c[1]), "+f"(c[2]), "+f"(c[3])
        : "r"(a[0]), "r"(a[1]), "r"(a[2]), "r"(a[3]), "r"(b[0]), "r"(b[1]));
}

// ---------------- GEMM: C[m,n] = sum_k A[m,k] * B[n,k] ----------------
// CTA 128x256, K-chunk 32, 2-stage cp.async. 8 warps (2M x 4N), warp 64x64.
#define PAD   36
#define ATILB (128 * PAD * 4)   // 18432 B
#define BTILB (256 * PAD * 4)   // 36864 B

template <int TERMS, bool ASPLIT, bool CSPLIT>
__global__ __launch_bounds__(256, 1)
void gemm_tc(const float* __restrict__ Ahg, const float* __restrict__ Alg,
             const float* __restrict__ Bhg, const float* __restrict__ Blg,
             float* __restrict__ Cg, float* __restrict__ C2g,
             int K, int N, long long sA, long long sB, long long sC)
{
    constexpr int T_AH = 0;
    constexpr int T_AL = ATILB;                       // unused if !ASPLIT
    constexpr int T_BH = ASPLIT ? 2 * ATILB : ATILB;
    constexpr int T_BL = T_BH + BTILB;
    constexpr int STG  = T_BL + BTILB;                // stage bytes

    extern __shared__ char smc[];
    const uint32_t sb = smem_u32(smc);

    const int tid  = threadIdx.x;
    const int wid  = tid >> 5;
    const int lane = tid & 31;
    const int g    = lane >> 2;
    const int tg   = lane & 3;
    const int wm   = (wid >> 2) * 64;   // 0 / 64
    const int wn   = (wid & 3) * 64;    // 0 / 64 / 128 / 192

    const long long aoff = blockIdx.z * sA + (long long)(blockIdx.y * 128) * K;
    const long long boff = blockIdx.z * sB + (long long)(blockIdx.x * 256) * K;
    const float* Ah = Ahg + aoff;
    const float* Al = Alg + aoff;
    const float* Bh = Bhg + boff;
    const float* Bl = Blg + boff;

    float acc[4][8][4];
#pragma unroll
    for (int mt = 0; mt < 4; ++mt)
#pragma unroll
        for (int nt = 0; nt < 8; ++nt)
#pragma unroll
            for (int q = 0; q < 4; ++q) acc[mt][nt][q] = 0.f;

    const int nc = K >> 5;
    const int lr = tid >> 3;         // 0..31
    const int lc = (tid & 7) * 4;    // 0..28

    auto stage_load = [&](int i, int s) {
        const int kt = i << 5;
        const uint32_t st = sb + (uint32_t)(s * STG);
#pragma unroll
        for (int p = 0; p < 4; ++p) {
            const int r = lr + p * 32;
            const uint32_t off = (uint32_t)((r * PAD + lc) * 4);
            const long long gi = (long long)r * K + kt + lc;
            CP_ASYNC16(st + T_AH + off, Ah + gi);
            if (ASPLIT) CP_ASYNC16(st + T_AL + off, Al + gi);
        }
#pragma unroll
        for (int p = 0; p < 8; ++p) {
            const int r = lr + p * 32;
            const uint32_t off = (uint32_t)((r * PAD + lc) * 4);
            const long long gi = (long long)r * K + kt + lc;
            CP_ASYNC16(st + T_BH + off, Bh + gi);
            CP_ASYNC16(st + T_BL + off, Bl + gi);
        }
    };

    stage_load(0, 0); CP_COMMIT();
    if (nc > 1) { stage_load(1, 1); }
    CP_COMMIT();

    for (int i = 0; i < nc; ++i) {
        if (i + 2 < nc) { CP_WAIT(1); } else { CP_WAIT(0); }
        __syncthreads();

        const char* stg = smc + (i & 1) * STG;
        const float* AHs = (const float*)(stg + T_AH);
        const float* ALs = (const float*)(stg + T_AL);
        const float* BHs = (const float*)(stg + T_BH);
        const float* BLs = (const float*)(stg + T_BL);

#pragma unroll
        for (int ks = 0; ks < 4; ++ks) {
            const int k0 = ks * 8;

            uint32_t ahi[4][4], alo[4][4];
#pragma unroll
            for (int mt = 0; mt < 4; ++mt) {
                const int r0 = wm + mt * 16 + g;
                const int i00 = r0 * PAD + k0 + tg;
                const int i10 = (r0 + 8) * PAD + k0 + tg;
                if (ASPLIT) {
                    ahi[mt][0] = __float_as_uint(AHs[i00]);
                    ahi[mt][1] = __float_as_uint(AHs[i10]);
                    ahi[mt][2] = __float_as_uint(AHs[i00 + 4]);
                    ahi[mt][3] = __float_as_uint(AHs[i10 + 4]);
                    alo[mt][0] = __float_as_uint(ALs[i00]);
                    alo[mt][1] = __float_as_uint(ALs[i10]);
                    alo[mt][2] = __float_as_uint(ALs[i00 + 4]);
                    alo[mt][3] = __float_as_uint(ALs[i10 + 4]);
                } else {
                    asm("cvt.rna.tf32.f32 %0, %1;" : "=r"(ahi[mt][0]) : "f"(AHs[i00]));
                    asm("cvt.rna.tf32.f32 %0, %1;" : "=r"(ahi[mt][1]) : "f"(AHs[i10]));
                    asm("cvt.rna.tf32.f32 %0, %1;" : "=r"(ahi[mt][2]) : "f"(AHs[i00 + 4]));
                    asm("cvt.rna.tf32.f32 %0, %1;" : "=r"(ahi[mt][3]) : "f"(AHs[i10 + 4]));
                }
            }

#pragma unroll
            for (int h = 0; h < 2; ++h) {
                uint32_t bhi[4][2], blo[4][2];
#pragma unroll
                for (int nt = 0; nt < 4; ++nt) {
                    const int n0 = (wn + h * 32 + nt * 8 + g) * PAD + k0 + tg;
                    bhi[nt][0] = __float_as_uint(BHs[n0]);
                    bhi[nt][1] = __float_as_uint(BHs[n0 + 4]);
                    blo[nt][0] = __float_as_uint(BLs[n0]);
                    blo[nt][1] = __float_as_uint(BLs[n0 + 4]);
                }
#pragma unroll
                for (int mt = 0; mt < 4; ++mt)
#pragma unroll
                    for (int nt = 0; nt < 4; ++nt) {
                        float* a = acc[mt][h * 4 + nt];
                        mma8(a, ahi[mt], bhi[nt]);
                        if (TERMS >= 2) mma8(a, ahi[mt], blo[nt]);
                        if (TERMS >= 3) mma8(a, alo[mt], bhi[nt]);
                    }
            }
        }
        __syncthreads();
        if (i + 2 < nc) { stage_load(i + 2, i & 1); CP_COMMIT(); }
    }

    // ---- epilogue ----
    const long long crow = blockIdx.z * sC
                         + (long long)(blockIdx.y * 128 + wm) * N + blockIdx.x * 256 + wn;
    if (CSPLIT) {
        float* C  = Cg  + crow;
        float* C2 = C2g + crow;
#pragma unroll
        for (int mt = 0; mt < 4; ++mt)
#pragma unroll
            for (int nt = 0; nt < 8; ++nt) {
                const long long r0 = (long long)(mt * 16 + g) * N + nt * 8 + 2 * tg;
                const long long r1 = r0 + 8LL * N;
                float2 p0 = splitf(acc[mt][nt][0]), p1 = splitf(acc[mt][nt][1]);
                float2 p2 = splitf(acc[mt][nt][2]), p3 = splitf(acc[mt][nt][3]);
                *(float2*)&C [r0] = make_float2(p0.x, p1.x);
                *(float2*)&C2[r0] = make_float2(p0.y, p1.y);
                *(float2*)&C [r1] = make_float2(p2.x, p3.x);
                *(float2*)&C2[r1] = make_float2(p2.y, p3.y);
            }
    } else {
        float* C = Cg + crow;
#pragma unroll
        for (int mt = 0; mt < 4; ++mt)
#pragma unroll
            for (int nt = 0; nt < 8; ++nt) {
                const long long r0 = (long long)(mt * 16 + g) * N + nt * 8 + 2 * tg;
                const long long r1 = r0 + 8LL * N;
                *(float2*)&C[r0] = make_float2(acc[mt][nt][0], acc[mt][nt][1]);
                *(float2*)&C[r1] = make_float2(acc[mt][nt][2], acc[mt][nt][3]);
            }
    }
}

// ---------------- pre-split into two arrays ----------------
__global__ __launch_bounds__(256)
void split_two(const float4* __restrict__ in, float4* __restrict__ oh,
               float4* __restrict__ ol, long long n4)
{
    const long long i = (long long)blockIdx.x * blockDim.x + threadIdx.x;
    if (i >= n4) return;
    float4 v = in[i];
    float2 a = splitf(v.x), b = splitf(v.y), c = splitf(v.z), d = splitf(v.w);
    oh[i] = make_float4(a.x, b.x, c.x, d.x);
    ol[i] = make_float4(a.y, b.y, c.y, d.y);
}

// ------- transpose + split: outh/outl[c][r] = split(in[r][c]) -------
__global__ __launch_bounds__(256)
void transpose_split2(const float* __restrict__ in, float* __restrict__ outh,
                      float* __restrict__ outl, int R, int C)
{
    __shared__ float t[32][33];
    const long long zo = (long long)blockIdx.z * R * C;
    in += zo; outh += zo; outl += zo;
    const int c0 = blockIdx.x * 32, r0 = blockIdx.y * 32;
#pragma unroll
    for (int dy = 0; dy < 32; dy += 8)
        t[threadIdx.y + dy][threadIdx.x] =
            in[(long long)(r0 + threadIdx.y + dy) * C + c0 + threadIdx.x];
    __syncthreads();
#pragma unroll
    for (int dy = 0; dy < 32; dy += 8) {
        float2 s = splitf(t[threadIdx.x][threadIdx.y + dy]);
        const long long o = (long long)(c0 + threadIdx.y + dy) * R + r0 + threadIdx.x;
        outh[o] = s.x;
        outl[o] = s.y;
    }
}

// ---------------- softmax over rows of length 2048, in place ----------------
__global__ __launch_bounds__(256)
void softmax_rows(float* __restrict__ data)
{
    const int S = 2048;
    float* p = data + (long long)blockIdx.x * S;
    const int tid = threadIdx.x;

    float4 v0 = ((const float4*)p)[tid];
    float4 v1 = ((const float4*)p)[tid + 256];

    float m = fmaxf(fmaxf(fmaxf(v0.x, v0.y), fmaxf(v0.z, v0.w)),
                    fmaxf(fmaxf(v1.x, v1.y), fmaxf(v1.z, v1.w)));

    __shared__ float red[8];
#pragma unroll
    for (int o = 16; o > 0; o >>= 1) m = fmaxf(m, __shfl_xor_sync(~0u, m, o));
    if ((tid & 31) == 0) red[tid >> 5] = m;
    __syncthreads();
    {
        float t = (tid < 8) ? red[tid & 7] : -1e30f;
#pragma unroll
        for (int o = 4; o > 0; o >>= 1) t = fmaxf(t, __shfl_xor_sync(~0u, t, o));
        __syncthreads();
        if (tid == 0) red[0] = t;
        __syncthreads();
        m = red[0];
    }

    v0.x = __expf(v0.x - m); v0.y = __expf(v0.y - m);
    v0.z = __expf(v0.z - m); v0.w = __expf(v0.w - m);
    v1.x = __expf(v1.x - m); v1.y = __expf(v1.y - m);
    v1.z = __expf(v1.z - m); v1.w = __expf(v1.w - m);

    float s = v0.x + v0.y + v0.z + v0.w + v1.x + v1.y + v1.z + v1.w;
#pragma unroll
    for (int o = 16; o > 0; o >>= 1) s += __shfl_xor_sync(~0u, s, o);
    __syncthreads();
    if ((tid & 31) == 0) red[tid >> 5] = s;
    __syncthreads();
    {
        float t = (tid < 8) ? red[tid & 7] : 0.f;
#pragma unroll
        for (int o = 4; o > 0; o >>= 1) t += __shfl_xor_sync(~0u, t, o);
        __syncthreads();
        if (tid == 0) red[0] = t;
        __syncthreads();
        s = red[0];
    }

    const float inv = 1.0f / s;
    v0.x *= inv; v0.y *= inv; v0.z *= inv; v0.w *= inv;
    v1.x *= inv; v1.y *= inv; v1.z *= inv; v1.w *= inv;

    ((float4*)p)[tid]       = v0;
    ((float4*)p)[tid + 256] = v1;
}

// ---------------- launch ----------------
extern "C" void kernel_launch(void* const* d_in, const int* in_sizes, int n_in,
                              void* d_out, int out_size)
{
    const float* x = (const float*)d_in[0];   // [8,2048,1024]
    const float* w = (const float*)d_in[1];   // [1024,1024]
    float* ctx  = (float*)d_out;              // [8,2048,1024]
    float* attn = (float*)d_out + 16777216LL; // [8,2048,2048]

    float *xh, *xl, *xth, *xtl, *wth, *wtl, *xwh, *xwl;
    cudaGetSymbolAddress((void**)&xh,  g_xh);
    cudaGetSymbolAddress((void**)&xl,  g_xl);
    cudaGetSymbolAddress((void**)&xth, g_xth);
    cudaGetSymbolAddress((void**)&xtl, g_xtl);
    cudaGetSymbolAddress((void**)&wth, g_wth);
    cudaGetSymbolAddress((void**)&wtl, g_wtl);
    cudaGetSymbolAddress((void**)&xwh, g_xwh);
    cudaGetSymbolAddress((void**)&xwl, g_xwl);

    const int B = 8, S = 2048, H = 1024;

    const int SM_SPLIT = 2 * (2 * ATILB + 2 * BTILB);  // 221184
    const int SM_RAW   = 2 * (ATILB + 2 * BTILB);      // 184320
    cudaFuncSetAttribute(gemm_tc<3, true,  true >, cudaFuncAttributeMaxDynamicSharedMemorySize, SM_SPLIT);
    cudaFuncSetAttribute(gemm_tc<3, true,  false>, cudaFuncAttributeMaxDynamicSharedMemorySize, SM_SPLIT);
    cudaFuncSetAttribute(gemm_tc<2, false, false>, cudaFuncAttributeMaxDynamicSharedMemorySize, SM_RAW);

    // pre-splits
    {
        long long n4 = (long long)B * S * H / 4;
        split_two<<<(unsigned)((n4 + 255) / 256), 256>>>(
            (const float4*)x, (float4*)xh, (float4*)xl, n4);
    }
    transpose_split2<<<dim3(H / 32, S / 32, B), dim3(32, 8)>>>(x, xth, xtl, S, H);
    transpose_split2<<<dim3(H / 32, H / 32, 1), dim3(32, 8)>>>(w, wth, wtl, H, H);

    // 1) xw = x @ W -> split xwh/xwl.
    gemm_tc<3, true, true><<<dim3(H / 256, (B * S) / 128, 1), 256, SM_SPLIT>>>(
        xh, xl, wth, wtl, xwh, xwl, H, H, 0, 0, 0);

    // 2) scores = xw @ x^T -> attn buffer (per batch).
    gemm_tc<3, true, false><<<dim3(S / 256, S / 128, B), 256, SM_SPLIT>>>(
        xwh, xwl, xh, xl, attn, nullptr, H, S,
        (long long)S * H, (long long)S * H, (long long)S * S);

    // 3) softmax in place
    softmax_rows<<<B * S, 256>>>(attn);

    // 4) ctx = attn @ x. A raw (tf32 on the fly), 2 terms.
    gemm_tc<2, false, false><<<dim3(H / 256, S / 128, B), 256, SM_RAW>>>(
        attn, nullptr, xth, xtl, ctx, nullptr, S, H,
        (long long)S * S, (long long)S * H, (long long)S * H);
}